// round 14
// baseline (speedup 1.0000x reference)
#include <cuda_runtime.h>
#include <cuda_bf16.h>
#include <math.h>

// ---------------- problem constants ----------------
#define SEQ   10
#define WAY   5
#define SHOT  5
#define TT    45          // C(10,2)
#define D     2048
#define NQ    75
#define NS    25
#define NQT   3375        // NQ*TT
#define NST   1125        // NS*TT
#define QF    750         // query frames
#define NF    1000        // total frames

__constant__ int c_p0[TT] = {0,0,0,0,0,0,0,0,0, 1,1,1,1,1,1,1,1, 2,2,2,2,2,2,2,
                             3,3,3,3,3,3, 4,4,4,4,4, 5,5,5,5, 6,6,6, 7,7, 8};
__constant__ int c_p1[TT] = {1,2,3,4,5,6,7,8,9, 2,3,4,5,6,7,8,9, 3,4,5,6,7,8,9,
                             4,5,6,7,8,9, 5,6,7,8,9, 6,7,8,9, 7,8,9, 8,9, 9};

// ---------------- scratch ----------------
__device__ __nv_bfloat16 g_Fh[NF * D];       // frame hi
__device__ __nv_bfloat16 g_Fl[NF * D];       // frame lo
__device__ __nv_bfloat16 g_Wh[4096 * D];     // W rows remapped: n -> W[(n&2047)][(n&2048)+k]
__device__ __nv_bfloat16 g_Wl[4096 * D];
__device__ float g_EF[NF * 4096];            // per-frame projections fp32
__device__ __nv_bfloat16 g_QEh[NQT * D];     // q_embed hi/lo
__device__ __nv_bfloat16 g_QEl[NQT * D];
__device__ __nv_bfloat16 g_SEh[NST * D];
__device__ __nv_bfloat16 g_SEl[NST * D];
__device__ float g_qn[NQT];
__device__ float g_sn[NST];
__device__ float g_DQ[NQT * NST];
__device__ float g_SD[NST * NST];
__device__ float g_rowmax[WAY * NQT];
__device__ int   g_pos[WAY * NQT];
__device__ float g_ave[WAY * NQT];
__device__ int   g_record[WAY * NST];
__device__ float g_mask[WAY * NST];
__device__ float g_msum[WAY];
__device__ float g_contrast[NQ * WAY];

typedef unsigned long long u64;
typedef unsigned int u32;
typedef long long s64;

__device__ __forceinline__ u32 smem_u32(const void* p) {
    u32 a;
    asm("{ .reg .u64 t; cvta.to.shared.u64 t, %1; cvt.u32.u64 %0, t; }" : "=r"(a) : "l"(p));
    return a;
}

// ---------------- init (zeroes record/contrast; launched after dist GEMM) -------
__global__ void k_init() {
    int i = blockIdx.x * blockDim.x + threadIdx.x;
    if (i < WAY * NST) g_record[i] = 0;
    if (i < NQ * WAY)  g_contrast[i] = 0.f;
}

// ---------------- input hi/lo conversion (float4 vectorized) ----------------
__global__ void k_cvt(const float* __restrict__ q, const float* __restrict__ s,
                      const float* __restrict__ w) {
    int i4 = blockIdx.x * 256 + threadIdx.x;
    const int NFR4 = NF * D / 4;          // 512000
    const int NWE4 = 4096 * D / 4;        // 2097152
    __nv_bfloat16 *dh, *dl;
    float4 x;
    if (i4 < NFR4) {
        int base = i4 * 4;
        x = (base < QF * D) ? *(const float4*)(q + base)
                            : *(const float4*)(s + (base - QF * D));
        dh = g_Fh + base; dl = g_Fl + base;
    } else if (i4 < NFR4 + NWE4) {
        int j = (i4 - NFR4) * 4;
        int n = j >> 11, k = j & 2047;
        x = *(const float4*)(w + (size_t)(n & 2047) * 4096 + (n & 2048) + k);
        dh = g_Wh + j; dl = g_Wl + j;
    } else return;
    __nv_bfloat16 h0 = __float2bfloat16(x.x), h1 = __float2bfloat16(x.y);
    __nv_bfloat16 h2 = __float2bfloat16(x.z), h3 = __float2bfloat16(x.w);
    ((__nv_bfloat162*)dh)[0] = __nv_bfloat162(h0, h1);
    ((__nv_bfloat162*)dh)[1] = __nv_bfloat162(h2, h3);
    ((__nv_bfloat162*)dl)[0] = __nv_bfloat162(
        __float2bfloat16(x.x - __bfloat162float(h0)),
        __float2bfloat16(x.y - __bfloat162float(h1)));
    ((__nv_bfloat162*)dl)[1] = __nv_bfloat162(
        __float2bfloat16(x.z - __bfloat162float(h2)),
        __float2bfloat16(x.w - __bfloat162float(h3)));
}

// ---------------- mma.sync bf16 GEMM, K=6144 (hi/lo 3-term), 128x128 tiles ------
// Round-11 proven config (2-stage cp.async ring, 80B padded rows, B ldmatrix.x4),
// but 3 CTAs/SM: three independent barrier groups per SM hide the per-tile
// latency that pipeline depth could not (tensor 35% @ 2 CTAs, latency-bound).
// MODE 1: distance GEMMs (y<27: DQ A=QE; else SD A=SE; B=SE), sqrt epilogue.
// MODE 2: embedding GEMM: A=frames, B=remapped W, C=EF fp32.
#define STGB 20480        // bytes per stage: A 10240 + B 10240
#define NTILE 192         // 3 segments * 64 k-tiles (BK=32)

template<int MODE>
__global__ void __launch_bounds__(256, 3) gemm_mma() {
    __shared__ __align__(16) char smem[2 * STGB];
    int tid = threadIdx.x;
    int lane = tid & 31, wid = tid >> 5;
    int wm = wid & 1, wn = wid >> 1;

    int n0 = blockIdx.x * 128;
    int m0, Mloc, Nloc, ldc;
    const __nv_bfloat16 *Ah, *Al, *Bh, *Bl;
    const float *anp = nullptr, *bnp = nullptr;
    float* C;
    if (MODE == 1) {
        int y = blockIdx.y;
        if (y < 27) { m0 = y * 128;        Ah = g_QEh; Al = g_QEl; anp = g_qn; C = g_DQ; Mloc = NQT; }
        else        { m0 = (y - 27) * 128; Ah = g_SEh; Al = g_SEl; anp = g_sn; C = g_SD; Mloc = NST; }
        Bh = g_SEh; Bl = g_SEl; bnp = g_sn; Nloc = NST; ldc = NST;
    } else {
        m0 = blockIdx.y * 128;
        Ah = g_Fh; Al = g_Fl; Bh = g_Wh; Bl = g_Wl;
        C = g_EF; Mloc = NF; Nloc = 4096; ldc = 4096;
    }
    const s64 dAlo = (s64)(Al - Ah);      // element offset hi->lo
    const s64 dBlo = (s64)(Bl - Bh);

    // ---- loader slots: 2 A + 2 B 16B chunks per thread ----
    const __nv_bfloat16 *aP[2], *bP[2];
    u32 aDst[2], bDst[2];
#pragma unroll
    for (int i = 0; i < 2; i++) {
        int s = tid + i * 256;            // [0,512)
        int row = s >> 2, kc = s & 3;     // kc = 16B chunk within 32-elem k
        int r = m0 + row; int rc = (r < Mloc) ? r : 0;
        aP[i]   = Ah + (size_t)rc * D + kc * 8;
        aDst[i] = smem_u32(smem + row * 80 + kc * 16);
        int nr = n0 + row; int nc = (nr < Nloc) ? nr : 0;
        bP[i]   = Bh + (size_t)nc * D + kc * 8;
        bDst[i] = smem_u32(smem + 10240 + row * 80 + kc * 16);
    }

    // ---- ldmatrix source addresses (stage 0) ----
    u32 aLd[4], bLd[2];
#pragma unroll
    for (int mi = 0; mi < 4; mi++) {
        int rrow = wm * 64 + mi * 16 + (lane & 15);
        int rcol = (lane >> 4) * 8;       // elements
        aLd[mi] = smem_u32(smem + rrow * 80 + rcol * 2);
    }
#pragma unroll
    for (int nb = 0; nb < 2; nb++) {
        int brow = wn * 32 + nb * 16 + (lane & 7) + ((lane >> 4) & 1) * 8;
        int bcol = ((lane >> 3) & 1) * 8; // elements
        bLd[nb] = smem_u32(smem + 10240 + brow * 80 + bcol * 2);
    }

    float acc[4][4][4];
#pragma unroll
    for (int mi = 0; mi < 4; mi++)
#pragma unroll
        for (int ni = 0; ni < 4; ni++)
#pragma unroll
            for (int x = 0; x < 4; x++) acc[mi][ni][x] = 0.f;

    auto issue = [&](int t) {
        int seg = t >> 6;
        int kk = (t & 63) * 32;
        u32 so = (u32)(t & 1) * STGB;
        s64 ao = (seg < 2 ? 0 : dAlo) + kk;   // A segs: hi,hi,lo
        s64 bo = (seg == 1 ? dBlo : 0) + kk;  // B segs: hi,lo,hi
#pragma unroll
        for (int i = 0; i < 2; i++) {
            asm volatile("cp.async.cg.shared.global [%0], [%1], 16;"
                         :: "r"(aDst[i] + so), "l"(aP[i] + ao));
            asm volatile("cp.async.cg.shared.global [%0], [%1], 16;"
                         :: "r"(bDst[i] + so), "l"(bP[i] + bo));
        }
        asm volatile("cp.async.commit_group;");
    };

    issue(0);
    issue(1);

    for (int t = 0; t < NTILE; t++) {
        if (t + 1 < NTILE) asm volatile("cp.async.wait_group 1;");
        else               asm volatile("cp.async.wait_group 0;");
        __syncthreads();
        u32 so = (u32)(t & 1) * STGB;
#pragma unroll
        for (int ki = 0; ki < 2; ki++) {
            u32 af[4][4], bf_[2][4];
#pragma unroll
            for (int mi = 0; mi < 4; mi++)
                asm volatile("ldmatrix.sync.aligned.m8n8.x4.shared.b16 {%0,%1,%2,%3}, [%4];"
                    : "=r"(af[mi][0]), "=r"(af[mi][1]), "=r"(af[mi][2]), "=r"(af[mi][3])
                    : "r"(aLd[mi] + so + ki * 32));
#pragma unroll
            for (int nb = 0; nb < 2; nb++)
                asm volatile("ldmatrix.sync.aligned.m8n8.x4.shared.b16 {%0,%1,%2,%3}, [%4];"
                    : "=r"(bf_[nb][0]), "=r"(bf_[nb][1]), "=r"(bf_[nb][2]), "=r"(bf_[nb][3])
                    : "r"(bLd[nb] + so + ki * 32));
#pragma unroll
            for (int mi = 0; mi < 4; mi++)
#pragma unroll
                for (int ni = 0; ni < 4; ni++) {
                    u32 b0 = bf_[ni >> 1][(ni & 1) * 2];
                    u32 b1 = bf_[ni >> 1][(ni & 1) * 2 + 1];
                    asm volatile(
                        "mma.sync.aligned.m16n8k16.row.col.f32.bf16.bf16.f32 "
                        "{%0,%1,%2,%3}, {%4,%5,%6,%7}, {%8,%9}, {%0,%1,%2,%3};"
                        : "+f"(acc[mi][ni][0]), "+f"(acc[mi][ni][1]),
                          "+f"(acc[mi][ni][2]), "+f"(acc[mi][ni][3])
                        : "r"(af[mi][0]), "r"(af[mi][1]), "r"(af[mi][2]), "r"(af[mi][3]),
                          "r"(b0), "r"(b1));
                }
        }
        __syncthreads();
        if (t + 2 < NTILE) issue(t + 2);
    }

    // ---- epilogue ----
#pragma unroll
    for (int mi = 0; mi < 4; mi++) {
        int r0 = m0 + wm * 64 + mi * 16 + (lane >> 2);
        int r1 = r0 + 8;
        float an0 = 0.f, an1 = 0.f;
        if (MODE == 1) {
            an0 = (r0 < Mloc) ? anp[r0] : 0.f;
            an1 = (r1 < Mloc) ? anp[r1] : 0.f;
        }
#pragma unroll
        for (int ni = 0; ni < 4; ni++) {
            int c0 = n0 + wn * 32 + ni * 8 + (lane & 3) * 2;
            float v0 = acc[mi][ni][0], v1 = acc[mi][ni][1];
            float v2 = acc[mi][ni][2], v3 = acc[mi][ni][3];
            if (MODE == 1) {
                float b0 = (c0 < Nloc) ? bnp[c0] : 0.f;
                float b1 = (c0 + 1 < Nloc) ? bnp[c0 + 1] : 0.f;
                v0 = sqrtf(fmaxf(an0 + b0 - 2.f * v0, 0.f));
                v1 = sqrtf(fmaxf(an0 + b1 - 2.f * v1, 0.f));
                v2 = sqrtf(fmaxf(an1 + b0 - 2.f * v2, 0.f));
                v3 = sqrtf(fmaxf(an1 + b1 - 2.f * v3, 0.f));
            }
            if (r0 < Mloc) {
                if (c0 < Nloc)     C[(size_t)r0 * ldc + c0]     = v0;
                if (c0 + 1 < Nloc) C[(size_t)r0 * ldc + c0 + 1] = v1;
            }
            if (r1 < Mloc) {
                if (c0 < Nloc)     C[(size_t)r1 * ldc + c0]     = v2;
                if (c0 + 1 < Nloc) C[(size_t)r1 * ldc + c0 + 1] = v3;
            }
        }
    }
}

// ---------------- embedding build: relu(P[f0]+Q[f1]+b) -> hi/lo bf16 + norm ------
__global__ void k_embed(const float* __restrict__ bias) {
    int row = blockIdx.x;         // [0, NQT+NST)
    int tid = threadIdx.x;        // 256
    __nv_bfloat16 *dh, *dl;
    float* nout;
    int f0, f1;
    if (row < NQT) {
        int n = row / TT, t = row % TT;
        f0 = n * SEQ + c_p0[t];
        f1 = n * SEQ + c_p1[t];
        dh = g_QEh + (size_t)row * D; dl = g_QEl + (size_t)row * D; nout = &g_qn[row];
    } else {
        int si = row - NQT;
        int c = si / 225, rr = si % 225;
        int s = rr / TT, t = rr % TT;
        int base = QF + (c * SHOT + s) * SEQ;
        f0 = base + c_p0[t];
        f1 = base + c_p1[t];
        dh = g_SEh + (size_t)si * D; dl = g_SEl + (size_t)si * D; nout = &g_sn[si];
    }
    const float4* a0 = (const float4*)(g_EF + (size_t)f0 * 4096);          // P half
    const float4* a1 = (const float4*)(g_EF + (size_t)f1 * 4096 + D);      // Q half
    const float4* bb = (const float4*)bias;
    float nrm = 0.f;
    for (int v = tid; v < D / 4; v += 256) {
        float4 x = a0[v], y = a1[v], z = bb[v];
        float r0 = fmaxf(x.x + y.x + z.x, 0.f);
        float r1 = fmaxf(x.y + y.y + z.y, 0.f);
        float r2 = fmaxf(x.z + y.z + z.z, 0.f);
        float r3 = fmaxf(x.w + y.w + z.w, 0.f);
        nrm += r0 * r0 + r1 * r1 + r2 * r2 + r3 * r3;
        __nv_bfloat16 h0 = __float2bfloat16(r0), h1 = __float2bfloat16(r1);
        __nv_bfloat16 h2 = __float2bfloat16(r2), h3 = __float2bfloat16(r3);
        ((__nv_bfloat162*)dh)[v * 2]     = __nv_bfloat162(h0, h1);
        ((__nv_bfloat162*)dh)[v * 2 + 1] = __nv_bfloat162(h2, h3);
        ((__nv_bfloat162*)dl)[v * 2]     = __nv_bfloat162(
            __float2bfloat16(r0 - __bfloat162float(h0)),
            __float2bfloat16(r1 - __bfloat162float(h1)));
        ((__nv_bfloat162*)dl)[v * 2 + 1] = __nv_bfloat162(
            __float2bfloat16(r2 - __bfloat162float(h2)),
            __float2bfloat16(r3 - __bfloat162float(h3)));
    }
    __shared__ float sred[256];
    sred[tid] = nrm; __syncthreads();
    for (int s = 128; s; s >>= 1) {
        if (tid < s) sred[tid] += sred[tid + s];
        __syncthreads();
    }
    if (tid == 0) *nout = sred[0];
}

// ---------------- per-(class, query-tuple) reductions ----------------
__global__ void k_classred() {
    int w = (blockIdx.x * blockDim.x + threadIdx.x) >> 5;
    int lane = threadIdx.x & 31;
    if (w >= WAY * NQT) return;
    int c = w / NQT, qi = w % NQT;
    const float* row = g_DQ + (size_t)qi * NST + c * 225;
    float best = -1.f; int bidx = 0;
    float g0 = -1.f, g1 = -1.f, g2 = -1.f, g3 = -1.f, g4 = -1.f;
    for (int j = lane; j < 225; j += 32) {
        float v = row[j];
        if (v > best) { best = v; bidx = j; }
        int s = j % 5;
        if      (s == 0) g0 = fmaxf(g0, v);
        else if (s == 1) g1 = fmaxf(g1, v);
        else if (s == 2) g2 = fmaxf(g2, v);
        else if (s == 3) g3 = fmaxf(g3, v);
        else             g4 = fmaxf(g4, v);
    }
#pragma unroll
    for (int off = 16; off; off >>= 1) {
        float ob = __shfl_down_sync(0xffffffff, best, off);
        int   oi = __shfl_down_sync(0xffffffff, bidx, off);
        if (ob > best || (ob == best && oi < bidx)) { best = ob; bidx = oi; }
        g0 = fmaxf(g0, __shfl_down_sync(0xffffffff, g0, off));
        g1 = fmaxf(g1, __shfl_down_sync(0xffffffff, g1, off));
        g2 = fmaxf(g2, __shfl_down_sync(0xffffffff, g2, off));
        g3 = fmaxf(g3, __shfl_down_sync(0xffffffff, g3, off));
        g4 = fmaxf(g4, __shfl_down_sync(0xffffffff, g4, off));
    }
    if (lane == 0) {
        g_rowmax[w] = best;
        g_pos[w]    = bidx;
        g_ave[w]    = (g0 + g1 + g2 + g3 + g4) * 0.2f;
    }
}

// ---------------- record accumulation ----------------
__global__ void k_record() {
    int c = blockIdx.y;
    int tid = threadIdx.x;                 // 128
    __shared__ int srec[NST];
    for (int j = tid; j < NST; j += 128) srec[j] = 0;
    __syncthreads();
    int q0 = blockIdx.x * 125;
    for (int qi = q0; qi < q0 + 125; qi++) {
        int   p = g_pos[c * NQT + qi];
        float a = g_ave[c * NQT + qi];
        const float* row = g_SD + (size_t)(c * 225 + p) * NST;
        for (int j = tid; j < NST; j += 128)
            srec[j] += (row[j] > a) ? 1 : 0;
    }
    __syncthreads();
    for (int j = tid; j < NST; j += 128)
        atomicAdd(&g_record[c * NST + j], srec[j]);
}

// ---------------- threshold + mask + msum ----------------
__global__ void k_mask() {
    int c = blockIdx.x;
    int tid = threadIdx.x;                 // 256
    __shared__ float sred[256];
    __shared__ int   snz[256];
    __shared__ float s_thr;
    float msum_acc = 0.f;
    for (int m = 0; m < WAY; m++) {
        if (m == c) {
            if (tid < 225) g_mask[c * NST + m * 225 + tid] = 0.f;
            continue;
        }
        int rec = 0;
        if (tid < 225) rec = g_record[c * NST + m * 225 + tid];
        sred[tid] = (tid < 225) ? (float)rec : 0.f;
        snz[tid]  = (tid < 225 && rec != 0) ? 1 : 0;
        __syncthreads();
        for (int s = 128; s; s >>= 1) {
            if (tid < s) { sred[tid] += sred[tid + s]; snz[tid] += snz[tid + s]; }
            __syncthreads();
        }
        if (tid == 0) s_thr = sred[0] / fmaxf((float)snz[0], 1.f);
        __syncthreads();
        if (tid < 225) {
            float mk = ((float)rec < s_thr) ? 1.f : 0.f;
            g_mask[c * NST + m * 225 + tid] = mk;
            msum_acc += mk;
        }
        __syncthreads();
    }
    sred[tid] = msum_acc; __syncthreads();
    for (int s = 128; s; s >>= 1) {
        if (tid < s) sred[tid] += sred[tid + s];
        __syncthreads();
    }
    if (tid == 0) g_msum[c] = fmaxf(sred[0], 1.f);
}

// ---------------- masked mean -> contrast ----------------
__global__ void k_contrast() {
    int qi = blockIdx.x;
    int tid = threadIdx.x;                 // 128
    const float* row = g_DQ + (size_t)qi * NST;
    float a0 = 0.f, a1 = 0.f, a2 = 0.f, a3 = 0.f, a4 = 0.f;
    for (int j = tid; j < NST; j += 128) {
        float d = row[j];
        a0 += d * g_mask[0 * NST + j];
        a1 += d * g_mask[1 * NST + j];
        a2 += d * g_mask[2 * NST + j];
        a3 += d * g_mask[3 * NST + j];
        a4 += d * g_mask[4 * NST + j];
    }
    __shared__ float red[WAY][128];
    red[0][tid] = a0; red[1][tid] = a1; red[2][tid] = a2;
    red[3][tid] = a3; red[4][tid] = a4;
    __syncthreads();
    for (int s = 64; s; s >>= 1) {
        if (tid < s)
#pragma unroll
            for (int cc = 0; cc < WAY; cc++) red[cc][tid] += red[cc][tid + s];
        __syncthreads();
    }
    if (tid < WAY) {
        float val = red[tid][0] / g_msum[tid] * (1.f / (4.f * 45.f));
        atomicAdd(&g_contrast[(qi / TT) * WAY + tid], val);
    }
}

// ---------------- final outputs ----------------
__global__ void k_final(float* __restrict__ out, int out_size) {
    int idx = blockIdx.x * blockDim.x + threadIdx.x;
    if (idx >= NQ * WAY) return;
    int n = idx / WAY, c = idx % WAY;
    float s = 0.f;
    for (int t = 0; t < TT; t++) s += g_rowmax[c * NQT + n * TT + t];
    float dm = s * (1.f / 45.f);
    float ct = g_contrast[idx];
    float lg = dm / (ct + dm);
    if (idx < out_size) out[idx] = dm;
    if (NQ * WAY + idx < out_size) out[NQ * WAY + idx] = lg;
}

// ---------------- launch ----------------
extern "C" void kernel_launch(void* const* d_in, const int* in_sizes, int n_in,
                              void* d_out, int out_size) {
    const float* support = (const float*)d_in[0];   // [25,10,2048]
    const float* queries = (const float*)d_in[2];   // [75,10,2048]
    const float* W       = (const float*)d_in[3];   // [2048,4096]
    const float* bias    = (const float*)d_in[4];   // [2048]
    float* out = (float*)d_out;

    // hi/lo conversion (float4 vectorized)
    k_cvt<<<(NF * D / 4 + 4096 * D / 4 + 255) / 256, 256>>>(queries, support, W);

    // embedding GEMM: EF[1000, 4096] = frames @ Wmap^T  (mma.sync bf16, K=6144)
    gemm_mma<2><<<dim3(32, 8), 256>>>();

    k_embed<<<NQT + NST, 256>>>(bias);

    // distance GEMMs: y<27 DQ, y>=27 SD  (BN=128, 9x36 = 324 CTAs)
    gemm_mma<1><<<dim3(9, 36), 256>>>();

    // init only feeds k_record / k_contrast; launched late (ncu window lands on GEMMs)
    k_init<<<22, 256>>>();

    k_classred<<<2110, 256>>>();
    k_record<<<dim3(27, WAY), 128>>>();
    k_mask<<<WAY, 256>>>();
    k_contrast<<<NQT, 128>>>();
    k_final<<<2, 256>>>(out, out_size);
}

// round 15
// speedup vs baseline: 1.7372x; 1.7372x over previous
#include <cuda_runtime.h>
#include <cuda_bf16.h>
#include <math.h>

// ---------------- problem constants ----------------
#define SEQ   10
#define WAY   5
#define SHOT  5
#define TT    45          // C(10,2)
#define D     2048
#define NQ    75
#define NS    25
#define NQT   3375        // NQ*TT
#define NST   1125        // NS*TT
#define QF    750         // query frames
#define NF    1000        // total frames

__constant__ int c_p0[TT] = {0,0,0,0,0,0,0,0,0, 1,1,1,1,1,1,1,1, 2,2,2,2,2,2,2,
                             3,3,3,3,3,3, 4,4,4,4,4, 5,5,5,5, 6,6,6, 7,7, 8};
__constant__ int c_p1[TT] = {1,2,3,4,5,6,7,8,9, 2,3,4,5,6,7,8,9, 3,4,5,6,7,8,9,
                             4,5,6,7,8,9, 5,6,7,8,9, 6,7,8,9, 7,8,9, 8,9, 9};

// ---------------- scratch ----------------
__device__ __nv_bfloat16 g_Fh[NF * D];       // frame hi
__device__ __nv_bfloat16 g_Fl[NF * D];       // frame lo
__device__ __nv_bfloat16 g_Wh[4096 * D];     // W rows remapped: n -> W[(n&2047)][(n&2048)+k]
__device__ __nv_bfloat16 g_Wl[4096 * D];
__device__ float g_EF[NF * 4096];            // per-frame projections fp32
__device__ __nv_bfloat16 g_QEh[NQT * D];     // q_embed hi/lo
__device__ __nv_bfloat16 g_QEl[NQT * D];
__device__ __nv_bfloat16 g_SEh[NST * D];
__device__ __nv_bfloat16 g_SEl[NST * D];
__device__ float g_qn[NQT];
__device__ float g_sn[NST];
__device__ float g_DQ[NQT * NST];
__device__ float g_SD[NST * NST];
__device__ float g_rowmax[WAY * NQT];
__device__ int   g_pos[WAY * NQT];
__device__ float g_ave[WAY * NQT];
__device__ int   g_record[WAY * NST];
__device__ float g_mask[WAY * NST];
__device__ float g_msum[WAY];
__device__ float g_contrast[NQ * WAY];

typedef unsigned long long u64;
typedef unsigned int u32;
typedef long long s64;

__device__ __forceinline__ u32 smem_u32(const void* p) {
    u32 a;
    asm("{ .reg .u64 t; cvta.to.shared.u64 t, %1; cvt.u32.u64 %0, t; }" : "=r"(a) : "l"(p));
    return a;
}

// ---------------- init (zeroes record/contrast; launched after dist GEMM) -------
__global__ void k_init() {
    int i = blockIdx.x * blockDim.x + threadIdx.x;
    if (i < WAY * NST) g_record[i] = 0;
    if (i < NQ * WAY)  g_contrast[i] = 0.f;
}

// ---------------- input hi/lo conversion (float4 vectorized) ----------------
__global__ void k_cvt(const float* __restrict__ q, const float* __restrict__ s,
                      const float* __restrict__ w) {
    int i4 = blockIdx.x * 256 + threadIdx.x;
    const int NFR4 = NF * D / 4;          // 512000
    const int NWE4 = 4096 * D / 4;        // 2097152
    __nv_bfloat16 *dh, *dl;
    float4 x;
    if (i4 < NFR4) {
        int base = i4 * 4;
        x = (base < QF * D) ? *(const float4*)(q + base)
                            : *(const float4*)(s + (base - QF * D));
        dh = g_Fh + base; dl = g_Fl + base;
    } else if (i4 < NFR4 + NWE4) {
        int j = (i4 - NFR4) * 4;
        int n = j >> 11, k = j & 2047;
        x = *(const float4*)(w + (size_t)(n & 2047) * 4096 + (n & 2048) + k);
        dh = g_Wh + j; dl = g_Wl + j;
    } else return;
    __nv_bfloat16 h0 = __float2bfloat16(x.x), h1 = __float2bfloat16(x.y);
    __nv_bfloat16 h2 = __float2bfloat16(x.z), h3 = __float2bfloat16(x.w);
    ((__nv_bfloat162*)dh)[0] = __nv_bfloat162(h0, h1);
    ((__nv_bfloat162*)dh)[1] = __nv_bfloat162(h2, h3);
    ((__nv_bfloat162*)dl)[0] = __nv_bfloat162(
        __float2bfloat16(x.x - __bfloat162float(h0)),
        __float2bfloat16(x.y - __bfloat162float(h1)));
    ((__nv_bfloat162*)dl)[1] = __nv_bfloat162(
        __float2bfloat16(x.z - __bfloat162float(h2)),
        __float2bfloat16(x.w - __bfloat162float(h3)));
}

// ---------------- mma.sync bf16 GEMM, K=6144 (hi/lo 3-term), 128x128 tiles ------
// Round-11 proven core: 2-stage cp.async ring, 80B padded rows, B ldmatrix.x4, 2 CTA/SM.
// MODE 1: distance GEMMs, 1-D grid of 288 CTAs (one full 2-CTA/SM wave):
//         bid<243: DQ tile (A=QE, rows bid/9, cols bid%9).
//         bid>=243: SD upper-triangle tile (i<=j); off-diagonal results are
//         mirrored into the transpose (dot(a,b) bitwise == dot(b,a)).
// MODE 2: embedding GEMM: A=frames, B=remapped W, C=EF fp32.
#define STGB 20480        // bytes per stage: A 10240 + B 10240
#define NTILE 192         // 3 segments * 64 k-tiles (BK=32)

template<int MODE>
__global__ void __launch_bounds__(256, 2) gemm_mma() {
    __shared__ __align__(16) char smem[2 * STGB];
    int tid = threadIdx.x;
    int lane = tid & 31, wid = tid >> 5;
    int wm = wid & 1, wn = wid >> 1;

    int m0, n0, Mloc, Nloc, ldc;
    const __nv_bfloat16 *Ah, *Al, *Bh, *Bl;
    const float *anp = nullptr, *bnp = nullptr;
    float* C;
    bool mirror = false;
    if (MODE == 1) {
        int bid = blockIdx.x;
        if (bid < 243) {
            m0 = (bid / 9) * 128; n0 = (bid % 9) * 128;
            Ah = g_QEh; Al = g_QEl; anp = g_qn; C = g_DQ; Mloc = NQT;
        } else {
            int idx = bid - 243, i = 0;          // upper-triangle pair (i<=j) of 9
            while (idx >= 9 - i) { idx -= 9 - i; i++; }
            int j = i + idx;
            m0 = i * 128; n0 = j * 128;
            mirror = (i < j);
            Ah = g_SEh; Al = g_SEl; anp = g_sn; C = g_SD; Mloc = NST;
        }
        Bh = g_SEh; Bl = g_SEl; bnp = g_sn; Nloc = NST; ldc = NST;
    } else {
        m0 = blockIdx.y * 128; n0 = blockIdx.x * 128;
        Ah = g_Fh; Al = g_Fl; Bh = g_Wh; Bl = g_Wl;
        C = g_EF; Mloc = NF; Nloc = 4096; ldc = 4096;
    }
    const s64 dAlo = (s64)(Al - Ah);      // element offset hi->lo
    const s64 dBlo = (s64)(Bl - Bh);

    // ---- loader slots: 2 A + 2 B 16B chunks per thread ----
    const __nv_bfloat16 *aP[2], *bP[2];
    u32 aDst[2], bDst[2];
#pragma unroll
    for (int i = 0; i < 2; i++) {
        int s = tid + i * 256;            // [0,512)
        int row = s >> 2, kc = s & 3;     // kc = 16B chunk within 32-elem k
        int r = m0 + row; int rc = (r < Mloc) ? r : 0;
        aP[i]   = Ah + (size_t)rc * D + kc * 8;
        aDst[i] = smem_u32(smem + row * 80 + kc * 16);
        int nr = n0 + row; int nc = (nr < Nloc) ? nr : 0;
        bP[i]   = Bh + (size_t)nc * D + kc * 8;
        bDst[i] = smem_u32(smem + 10240 + row * 80 + kc * 16);
    }

    // ---- ldmatrix source addresses (stage 0) ----
    u32 aLd[4], bLd[2];
#pragma unroll
    for (int mi = 0; mi < 4; mi++) {
        int rrow = wm * 64 + mi * 16 + (lane & 15);
        int rcol = (lane >> 4) * 8;       // elements
        aLd[mi] = smem_u32(smem + rrow * 80 + rcol * 2);
    }
#pragma unroll
    for (int nb = 0; nb < 2; nb++) {
        int brow = wn * 32 + nb * 16 + (lane & 7) + ((lane >> 4) & 1) * 8;
        int bcol = ((lane >> 3) & 1) * 8; // elements
        bLd[nb] = smem_u32(smem + 10240 + brow * 80 + bcol * 2);
    }

    float acc[4][4][4];
#pragma unroll
    for (int mi = 0; mi < 4; mi++)
#pragma unroll
        for (int ni = 0; ni < 4; ni++)
#pragma unroll
            for (int x = 0; x < 4; x++) acc[mi][ni][x] = 0.f;

    auto issue = [&](int t) {
        int seg = t >> 6;
        int kk = (t & 63) * 32;
        u32 so = (u32)(t & 1) * STGB;
        s64 ao = (seg < 2 ? 0 : dAlo) + kk;   // A segs: hi,hi,lo
        s64 bo = (seg == 1 ? dBlo : 0) + kk;  // B segs: hi,lo,hi
#pragma unroll
        for (int i = 0; i < 2; i++) {
            asm volatile("cp.async.cg.shared.global [%0], [%1], 16;"
                         :: "r"(aDst[i] + so), "l"(aP[i] + ao));
            asm volatile("cp.async.cg.shared.global [%0], [%1], 16;"
                         :: "r"(bDst[i] + so), "l"(bP[i] + bo));
        }
        asm volatile("cp.async.commit_group;");
    };

    issue(0);
    issue(1);

    for (int t = 0; t < NTILE; t++) {
        if (t + 1 < NTILE) asm volatile("cp.async.wait_group 1;");
        else               asm volatile("cp.async.wait_group 0;");
        __syncthreads();
        u32 so = (u32)(t & 1) * STGB;
#pragma unroll
        for (int ki = 0; ki < 2; ki++) {
            u32 af[4][4], bf_[2][4];
#pragma unroll
            for (int mi = 0; mi < 4; mi++)
                asm volatile("ldmatrix.sync.aligned.m8n8.x4.shared.b16 {%0,%1,%2,%3}, [%4];"
                    : "=r"(af[mi][0]), "=r"(af[mi][1]), "=r"(af[mi][2]), "=r"(af[mi][3])
                    : "r"(aLd[mi] + so + ki * 32));
#pragma unroll
            for (int nb = 0; nb < 2; nb++)
                asm volatile("ldmatrix.sync.aligned.m8n8.x4.shared.b16 {%0,%1,%2,%3}, [%4];"
                    : "=r"(bf_[nb][0]), "=r"(bf_[nb][1]), "=r"(bf_[nb][2]), "=r"(bf_[nb][3])
                    : "r"(bLd[nb] + so + ki * 32));
#pragma unroll
            for (int mi = 0; mi < 4; mi++)
#pragma unroll
                for (int ni = 0; ni < 4; ni++) {
                    u32 b0 = bf_[ni >> 1][(ni & 1) * 2];
                    u32 b1 = bf_[ni >> 1][(ni & 1) * 2 + 1];
                    asm volatile(
                        "mma.sync.aligned.m16n8k16.row.col.f32.bf16.bf16.f32 "
                        "{%0,%1,%2,%3}, {%4,%5,%6,%7}, {%8,%9}, {%0,%1,%2,%3};"
                        : "+f"(acc[mi][ni][0]), "+f"(acc[mi][ni][1]),
                          "+f"(acc[mi][ni][2]), "+f"(acc[mi][ni][3])
                        : "r"(af[mi][0]), "r"(af[mi][1]), "r"(af[mi][2]), "r"(af[mi][3]),
                          "r"(b0), "r"(b1));
                }
        }
        __syncthreads();
        if (t + 2 < NTILE) issue(t + 2);
    }

    // ---- epilogue ----
#pragma unroll
    for (int mi = 0; mi < 4; mi++) {
        int r0 = m0 + wm * 64 + mi * 16 + (lane >> 2);
        int r1 = r0 + 8;
        float an0 = 0.f, an1 = 0.f;
        if (MODE == 1) {
            an0 = (r0 < Mloc) ? anp[r0] : 0.f;
            an1 = (r1 < Mloc) ? anp[r1] : 0.f;
        }
#pragma unroll
        for (int ni = 0; ni < 4; ni++) {
            int c0 = n0 + wn * 32 + ni * 8 + (lane & 3) * 2;
            float v0 = acc[mi][ni][0], v1 = acc[mi][ni][1];
            float v2 = acc[mi][ni][2], v3 = acc[mi][ni][3];
            if (MODE == 1) {
                float b0 = (c0 < Nloc) ? bnp[c0] : 0.f;
                float b1 = (c0 + 1 < Nloc) ? bnp[c0 + 1] : 0.f;
                v0 = sqrtf(fmaxf(an0 + b0 - 2.f * v0, 0.f));
                v1 = sqrtf(fmaxf(an0 + b1 - 2.f * v1, 0.f));
                v2 = sqrtf(fmaxf(an1 + b0 - 2.f * v2, 0.f));
                v3 = sqrtf(fmaxf(an1 + b1 - 2.f * v3, 0.f));
            }
            if (r0 < Mloc) {
                if (c0 < Nloc)     C[(size_t)r0 * ldc + c0]     = v0;
                if (c0 + 1 < Nloc) C[(size_t)r0 * ldc + c0 + 1] = v1;
            }
            if (r1 < Mloc) {
                if (c0 < Nloc)     C[(size_t)r1 * ldc + c0]     = v2;
                if (c0 + 1 < Nloc) C[(size_t)r1 * ldc + c0 + 1] = v3;
            }
            if (MODE == 1 && mirror) {     // SD symmetry: store transpose too
                if (c0 < Nloc) {
                    if (r0 < Mloc) C[(size_t)c0 * ldc + r0] = v0;
                    if (r1 < Mloc) C[(size_t)c0 * ldc + r1] = v2;
                }
                if (c0 + 1 < Nloc) {
                    if (r0 < Mloc) C[(size_t)(c0 + 1) * ldc + r0] = v1;
                    if (r1 < Mloc) C[(size_t)(c0 + 1) * ldc + r1] = v3;
                }
            }
        }
    }
}

// ---------------- embedding build: relu(P[f0]+Q[f1]+b) -> hi/lo bf16 + norm ------
__global__ void k_embed(const float* __restrict__ bias) {
    int row = blockIdx.x;         // [0, NQT+NST)
    int tid = threadIdx.x;        // 256
    __nv_bfloat16 *dh, *dl;
    float* nout;
    int f0, f1;
    if (row < NQT) {
        int n = row / TT, t = row % TT;
        f0 = n * SEQ + c_p0[t];
        f1 = n * SEQ + c_p1[t];
        dh = g_QEh + (size_t)row * D; dl = g_QEl + (size_t)row * D; nout = &g_qn[row];
    } else {
        int si = row - NQT;
        int c = si / 225, rr = si % 225;
        int s = rr / TT, t = rr % TT;
        int base = QF + (c * SHOT + s) * SEQ;
        f0 = base + c_p0[t];
        f1 = base + c_p1[t];
        dh = g_SEh + (size_t)si * D; dl = g_SEl + (size_t)si * D; nout = &g_sn[si];
    }
    const float4* a0 = (const float4*)(g_EF + (size_t)f0 * 4096);          // P half
    const float4* a1 = (const float4*)(g_EF + (size_t)f1 * 4096 + D);      // Q half
    const float4* bb = (const float4*)bias;
    float nrm = 0.f;
    for (int v = tid; v < D / 4; v += 256) {
        float4 x = a0[v], y = a1[v], z = bb[v];
        float r0 = fmaxf(x.x + y.x + z.x, 0.f);
        float r1 = fmaxf(x.y + y.y + z.y, 0.f);
        float r2 = fmaxf(x.z + y.z + z.z, 0.f);
        float r3 = fmaxf(x.w + y.w + z.w, 0.f);
        nrm += r0 * r0 + r1 * r1 + r2 * r2 + r3 * r3;
        __nv_bfloat16 h0 = __float2bfloat16(r0), h1 = __float2bfloat16(r1);
        __nv_bfloat16 h2 = __float2bfloat16(r2), h3 = __float2bfloat16(r3);
        ((__nv_bfloat162*)dh)[v * 2]     = __nv_bfloat162(h0, h1);
        ((__nv_bfloat162*)dh)[v * 2 + 1] = __nv_bfloat162(h2, h3);
        ((__nv_bfloat162*)dl)[v * 2]     = __nv_bfloat162(
            __float2bfloat16(r0 - __bfloat162float(h0)),
            __float2bfloat16(r1 - __bfloat162float(h1)));
        ((__nv_bfloat162*)dl)[v * 2 + 1] = __nv_bfloat162(
            __float2bfloat16(r2 - __bfloat162float(h2)),
            __float2bfloat16(r3 - __bfloat162float(h3)));
    }
    __shared__ float sred[256];
    sred[tid] = nrm; __syncthreads();
    for (int s = 128; s; s >>= 1) {
        if (tid < s) sred[tid] += sred[tid + s];
        __syncthreads();
    }
    if (tid == 0) *nout = sred[0];
}

// ---------------- per-(class, query-tuple) reductions ----------------
__global__ void k_classred() {
    int w = (blockIdx.x * blockDim.x + threadIdx.x) >> 5;
    int lane = threadIdx.x & 31;
    if (w >= WAY * NQT) return;
    int c = w / NQT, qi = w % NQT;
    const float* row = g_DQ + (size_t)qi * NST + c * 225;
    float best = -1.f; int bidx = 0;
    float g0 = -1.f, g1 = -1.f, g2 = -1.f, g3 = -1.f, g4 = -1.f;
    for (int j = lane; j < 225; j += 32) {
        float v = row[j];
        if (v > best) { best = v; bidx = j; }
        int s = j % 5;
        if      (s == 0) g0 = fmaxf(g0, v);
        else if (s == 1) g1 = fmaxf(g1, v);
        else if (s == 2) g2 = fmaxf(g2, v);
        else if (s == 3) g3 = fmaxf(g3, v);
        else             g4 = fmaxf(g4, v);
    }
#pragma unroll
    for (int off = 16; off; off >>= 1) {
        float ob = __shfl_down_sync(0xffffffff, best, off);
        int   oi = __shfl_down_sync(0xffffffff, bidx, off);
        if (ob > best || (ob == best && oi < bidx)) { best = ob; bidx = oi; }
        g0 = fmaxf(g0, __shfl_down_sync(0xffffffff, g0, off));
        g1 = fmaxf(g1, __shfl_down_sync(0xffffffff, g1, off));
        g2 = fmaxf(g2, __shfl_down_sync(0xffffffff, g2, off));
        g3 = fmaxf(g3, __shfl_down_sync(0xffffffff, g3, off));
        g4 = fmaxf(g4, __shfl_down_sync(0xffffffff, g4, off));
    }
    if (lane == 0) {
        g_rowmax[w] = best;
        g_pos[w]    = bidx;
        g_ave[w]    = (g0 + g1 + g2 + g3 + g4) * 0.2f;
    }
}

// ---------------- record accumulation ----------------
__global__ void k_record() {
    int c = blockIdx.y;
    int tid = threadIdx.x;                 // 128
    __shared__ int srec[NST];
    for (int j = tid; j < NST; j += 128) srec[j] = 0;
    __syncthreads();
    int q0 = blockIdx.x * 125;
    for (int qi = q0; qi < q0 + 125; qi++) {
        int   p = g_pos[c * NQT + qi];
        float a = g_ave[c * NQT + qi];
        const float* row = g_SD + (size_t)(c * 225 + p) * NST;
        for (int j = tid; j < NST; j += 128)
            srec[j] += (row[j] > a) ? 1 : 0;
    }
    __syncthreads();
    for (int j = tid; j < NST; j += 128)
        atomicAdd(&g_record[c * NST + j], srec[j]);
}

// ---------------- threshold + mask + msum ----------------
__global__ void k_mask() {
    int c = blockIdx.x;
    int tid = threadIdx.x;                 // 256
    __shared__ float sred[256];
    __shared__ int   snz[256];
    __shared__ float s_thr;
    float msum_acc = 0.f;
    for (int m = 0; m < WAY; m++) {
        if (m == c) {
            if (tid < 225) g_mask[c * NST + m * 225 + tid] = 0.f;
            continue;
        }
        int rec = 0;
        if (tid < 225) rec = g_record[c * NST + m * 225 + tid];
        sred[tid] = (tid < 225) ? (float)rec : 0.f;
        snz[tid]  = (tid < 225 && rec != 0) ? 1 : 0;
        __syncthreads();
        for (int s = 128; s; s >>= 1) {
            if (tid < s) { sred[tid] += sred[tid + s]; snz[tid] += snz[tid + s]; }
            __syncthreads();
        }
        if (tid == 0) s_thr = sred[0] / fmaxf((float)snz[0], 1.f);
        __syncthreads();
        if (tid < 225) {
            float mk = ((float)rec < s_thr) ? 1.f : 0.f;
            g_mask[c * NST + m * 225 + tid] = mk;
            msum_acc += mk;
        }
        __syncthreads();
    }
    sred[tid] = msum_acc; __syncthreads();
    for (int s = 128; s; s >>= 1) {
        if (tid < s) sred[tid] += sred[tid + s];
        __syncthreads();
    }
    if (tid == 0) g_msum[c] = fmaxf(sred[0], 1.f);
}

// ---------------- masked mean -> contrast ----------------
__global__ void k_contrast() {
    int qi = blockIdx.x;
    int tid = threadIdx.x;                 // 128
    const float* row = g_DQ + (size_t)qi * NST;
    float a0 = 0.f, a1 = 0.f, a2 = 0.f, a3 = 0.f, a4 = 0.f;
    for (int j = tid; j < NST; j += 128) {
        float d = row[j];
        a0 += d * g_mask[0 * NST + j];
        a1 += d * g_mask[1 * NST + j];
        a2 += d * g_mask[2 * NST + j];
        a3 += d * g_mask[3 * NST + j];
        a4 += d * g_mask[4 * NST + j];
    }
    __shared__ float red[WAY][128];
    red[0][tid] = a0; red[1][tid] = a1; red[2][tid] = a2;
    red[3][tid] = a3; red[4][tid] = a4;
    __syncthreads();
    for (int s = 64; s; s >>= 1) {
        if (tid < s)
#pragma unroll
            for (int cc = 0; cc < WAY; cc++) red[cc][tid] += red[cc][tid + s];
        __syncthreads();
    }
    if (tid < WAY) {
        float val = red[tid][0] / g_msum[tid] * (1.f / (4.f * 45.f));
        atomicAdd(&g_contrast[(qi / TT) * WAY + tid], val);
    }
}

// ---------------- final outputs ----------------
__global__ void k_final(float* __restrict__ out, int out_size) {
    int idx = blockIdx.x * blockDim.x + threadIdx.x;
    if (idx >= NQ * WAY) return;
    int n = idx / WAY, c = idx % WAY;
    float s = 0.f;
    for (int t = 0; t < TT; t++) s += g_rowmax[c * NQT + n * TT + t];
    float dm = s * (1.f / 45.f);
    float ct = g_contrast[idx];
    float lg = dm / (ct + dm);
    if (idx < out_size) out[idx] = dm;
    if (NQ * WAY + idx < out_size) out[NQ * WAY + idx] = lg;
}

// ---------------- launch ----------------
extern "C" void kernel_launch(void* const* d_in, const int* in_sizes, int n_in,
                              void* d_out, int out_size) {
    const float* support = (const float*)d_in[0];   // [25,10,2048]
    const float* queries = (const float*)d_in[2];   // [75,10,2048]
    const float* W       = (const float*)d_in[3];   // [2048,4096]
    const float* bias    = (const float*)d_in[4];   // [2048]
    float* out = (float*)d_out;

    // hi/lo conversion (float4 vectorized)
    k_cvt<<<(NF * D / 4 + 4096 * D / 4 + 255) / 256, 256>>>(queries, support, W);

    // embedding GEMM: EF[1000, 4096] = frames @ Wmap^T  (mma.sync bf16, K=6144)
    gemm_mma<2><<<dim3(32, 8), 256>>>();

    k_embed<<<NQT + NST, 256>>>(bias);

    // distance GEMMs: 243 DQ tiles + 45 SD upper-triangle tiles = 288 CTAs (one wave)
    gemm_mma<1><<<288, 256>>>();

    // init only feeds k_record / k_contrast; launched late (ncu window lands on GEMMs)
    k_init<<<22, 256>>>();

    k_classred<<<2110, 256>>>();
    k_record<<<dim3(27, WAY), 128>>>();
    k_mask<<<WAY, 256>>>();
    k_contrast<<<NQT, 128>>>();
    k_final<<<2, 256>>>(out, out_size);
}

// round 16
// speedup vs baseline: 1.8790x; 1.0816x over previous
#include <cuda_runtime.h>
#include <cuda_bf16.h>
#include <math.h>

// ---------------- problem constants ----------------
#define SEQ   10
#define WAY   5
#define SHOT  5
#define TT    45          // C(10,2)
#define D     2048
#define NQ    75
#define NS    25
#define NQT   3375        // NQ*TT
#define NST   1125        // NS*TT
#define QF    750         // query frames
#define NF    1000        // total frames

__constant__ int c_p0[TT] = {0,0,0,0,0,0,0,0,0, 1,1,1,1,1,1,1,1, 2,2,2,2,2,2,2,
                             3,3,3,3,3,3, 4,4,4,4,4, 5,5,5,5, 6,6,6, 7,7, 8};
__constant__ int c_p1[TT] = {1,2,3,4,5,6,7,8,9, 2,3,4,5,6,7,8,9, 3,4,5,6,7,8,9,
                             4,5,6,7,8,9, 5,6,7,8,9, 6,7,8,9, 7,8,9, 8,9, 9};

// ---------------- scratch ----------------
__device__ __nv_bfloat16 g_Fh[NF * D];       // frame hi
__device__ __nv_bfloat16 g_Fl[NF * D];       // frame lo
__device__ __nv_bfloat16 g_Wh[4096 * D];     // W rows remapped: n -> W[(n&2047)][(n&2048)+k]
__device__ __nv_bfloat16 g_Wl[4096 * D];
__device__ float g_EF[NF * 4096];            // per-frame projections fp32
__device__ __nv_bfloat16 g_QEh[NQT * D];     // q_embed hi/lo
__device__ __nv_bfloat16 g_QEl[NQT * D];
__device__ __nv_bfloat16 g_SEh[NST * D];
__device__ __nv_bfloat16 g_SEl[NST * D];
__device__ float g_qn[NQT];
__device__ float g_sn[NST];
__device__ float g_DQ[NQT * NST];
__device__ float g_SD[NST * NST];
__device__ float g_rowmax[WAY * NQT];
__device__ int   g_pos[WAY * NQT];
__device__ float g_ave[WAY * NQT];
__device__ int   g_record[WAY * NST];
__device__ float g_mask[WAY * NST];
__device__ float g_msum[WAY];
__device__ float g_contrast[NQ * WAY];

typedef unsigned long long u64;
typedef unsigned int u32;
typedef long long s64;

__device__ __forceinline__ u32 smem_u32(const void* p) {
    u32 a;
    asm("{ .reg .u64 t; cvta.to.shared.u64 t, %1; cvt.u32.u64 %0, t; }" : "=r"(a) : "l"(p));
    return a;
}

// ---------------- init (zeroes record/contrast; launched after dist GEMM) -------
__global__ void k_init() {
    int i = blockIdx.x * blockDim.x + threadIdx.x;
    if (i < WAY * NST) g_record[i] = 0;
    if (i < NQ * WAY)  g_contrast[i] = 0.f;
}

// ---------------- input hi/lo conversion (float4 vectorized) ----------------
__global__ void k_cvt(const float* __restrict__ q, const float* __restrict__ s,
                      const float* __restrict__ w) {
    int i4 = blockIdx.x * 256 + threadIdx.x;
    const int NFR4 = NF * D / 4;          // 512000
    const int NWE4 = 4096 * D / 4;        // 2097152
    __nv_bfloat16 *dh, *dl;
    float4 x;
    if (i4 < NFR4) {
        int base = i4 * 4;
        x = (base < QF * D) ? *(const float4*)(q + base)
                            : *(const float4*)(s + (base - QF * D));
        dh = g_Fh + base; dl = g_Fl + base;
    } else if (i4 < NFR4 + NWE4) {
        int j = (i4 - NFR4) * 4;
        int n = j >> 11, k = j & 2047;
        x = *(const float4*)(w + (size_t)(n & 2047) * 4096 + (n & 2048) + k);
        dh = g_Wh + j; dl = g_Wl + j;
    } else return;
    __nv_bfloat16 h0 = __float2bfloat16(x.x), h1 = __float2bfloat16(x.y);
    __nv_bfloat16 h2 = __float2bfloat16(x.z), h3 = __float2bfloat16(x.w);
    ((__nv_bfloat162*)dh)[0] = __nv_bfloat162(h0, h1);
    ((__nv_bfloat162*)dh)[1] = __nv_bfloat162(h2, h3);
    ((__nv_bfloat162*)dl)[0] = __nv_bfloat162(
        __float2bfloat16(x.x - __bfloat162float(h0)),
        __float2bfloat16(x.y - __bfloat162float(h1)));
    ((__nv_bfloat162*)dl)[1] = __nv_bfloat162(
        __float2bfloat16(x.z - __bfloat162float(h2)),
        __float2bfloat16(x.w - __bfloat162float(h3)));
}

// ---------------- mma.sync bf16 GEMM, K=6144 (hi/lo 3-term), 128x128 tiles ------
// Proven 80B-stride layout + B ldmatrix.x4, but 3-stage DYNAMIC-smem ring (60 KB),
// ONE __syncthreads per tile, prefetch issued before compute.
// Safety: after the sync at tile t, all warps finished compute(t-1); stage
// (t-1)%3 == (t+2)%3 is the one issue(t+2) overwrites. wait_group: 1 / 0 tail.
// MODE 1: 1-D grid 288 CTAs: bid<243 DQ tile; bid>=243 SD upper-triangle tile
//         (off-diagonal mirrored: dot(a,b) bitwise == dot(b,a)).
// MODE 2: embedding GEMM: A=frames, B=remapped W, C=EF fp32.
#define STGB 20480        // bytes per stage: A 10240 + B 10240
#define NTILE 192         // 3 segments * 64 k-tiles (BK=32)
#define SMEM_DYN (3 * STGB)

template<int MODE>
__global__ void __launch_bounds__(256, 2) gemm_mma() {
    extern __shared__ __align__(16) char smem[];
    int tid = threadIdx.x;
    int lane = tid & 31, wid = tid >> 5;
    int wm = wid & 1, wn = wid >> 1;

    int m0, n0, Mloc, Nloc, ldc;
    const __nv_bfloat16 *Ah, *Al, *Bh, *Bl;
    const float *anp = nullptr, *bnp = nullptr;
    float* C;
    bool mirror = false;
    if (MODE == 1) {
        int bid = blockIdx.x;
        if (bid < 243) {
            m0 = (bid / 9) * 128; n0 = (bid % 9) * 128;
            Ah = g_QEh; Al = g_QEl; anp = g_qn; C = g_DQ; Mloc = NQT;
        } else {
            int idx = bid - 243, i = 0;          // upper-triangle pair (i<=j) of 9
            while (idx >= 9 - i) { idx -= 9 - i; i++; }
            int j = i + idx;
            m0 = i * 128; n0 = j * 128;
            mirror = (i < j);
            Ah = g_SEh; Al = g_SEl; anp = g_sn; C = g_SD; Mloc = NST;
        }
        Bh = g_SEh; Bl = g_SEl; bnp = g_sn; Nloc = NST; ldc = NST;
    } else {
        m0 = blockIdx.y * 128; n0 = blockIdx.x * 128;
        Ah = g_Fh; Al = g_Fl; Bh = g_Wh; Bl = g_Wl;
        C = g_EF; Mloc = NF; Nloc = 4096; ldc = 4096;
    }
    const s64 dAlo = (s64)(Al - Ah);      // element offset hi->lo
    const s64 dBlo = (s64)(Bl - Bh);

    // ---- loader slots: 2 A + 2 B 16B chunks per thread ----
    const __nv_bfloat16 *aP[2], *bP[2];
    u32 aDst[2], bDst[2];
#pragma unroll
    for (int i = 0; i < 2; i++) {
        int s = tid + i * 256;            // [0,512)
        int row = s >> 2, kc = s & 3;     // kc = 16B chunk within 32-elem k
        int r = m0 + row; int rc = (r < Mloc) ? r : 0;
        aP[i]   = Ah + (size_t)rc * D + kc * 8;
        aDst[i] = smem_u32(smem + row * 80 + kc * 16);
        int nr = n0 + row; int nc = (nr < Nloc) ? nr : 0;
        bP[i]   = Bh + (size_t)nc * D + kc * 8;
        bDst[i] = smem_u32(smem + 10240 + row * 80 + kc * 16);
    }

    // ---- ldmatrix source addresses (stage 0) ----
    u32 aLd[4], bLd[2];
#pragma unroll
    for (int mi = 0; mi < 4; mi++) {
        int rrow = wm * 64 + mi * 16 + (lane & 15);
        int rcol = (lane >> 4) * 8;       // elements
        aLd[mi] = smem_u32(smem + rrow * 80 + rcol * 2);
    }
#pragma unroll
    for (int nb = 0; nb < 2; nb++) {
        int brow = wn * 32 + nb * 16 + (lane & 7) + ((lane >> 4) & 1) * 8;
        int bcol = ((lane >> 3) & 1) * 8; // elements
        bLd[nb] = smem_u32(smem + 10240 + brow * 80 + bcol * 2);
    }

    float acc[4][4][4];
#pragma unroll
    for (int mi = 0; mi < 4; mi++)
#pragma unroll
        for (int ni = 0; ni < 4; ni++)
#pragma unroll
            for (int x = 0; x < 4; x++) acc[mi][ni][x] = 0.f;

    auto issue = [&](int t, u32 so) {
        int seg = t >> 6;
        int kk = (t & 63) * 32;
        s64 ao = (seg < 2 ? 0 : dAlo) + kk;   // A segs: hi,hi,lo
        s64 bo = (seg == 1 ? dBlo : 0) + kk;  // B segs: hi,lo,hi
#pragma unroll
        for (int i = 0; i < 2; i++) {
            asm volatile("cp.async.cg.shared.global [%0], [%1], 16;"
                         :: "r"(aDst[i] + so), "l"(aP[i] + ao));
            asm volatile("cp.async.cg.shared.global [%0], [%1], 16;"
                         :: "r"(bDst[i] + so), "l"(bP[i] + bo));
        }
        asm volatile("cp.async.commit_group;");
    };

    issue(0, 0);
    issue(1, STGB);

    u32 soC = 0;            // stage offset of tile t
    u32 soI = 2 * STGB;     // stage offset of tile t+2
    for (int t = 0; t < NTILE; t++) {
        if (t + 1 < NTILE) asm volatile("cp.async.wait_group 1;");
        else               asm volatile("cp.async.wait_group 0;");
        __syncthreads();
        if (t + 2 < NTILE) issue(t + 2, soI);
#pragma unroll
        for (int ki = 0; ki < 2; ki++) {
            u32 af[4][4], bf_[2][4];
#pragma unroll
            for (int mi = 0; mi < 4; mi++)
                asm volatile("ldmatrix.sync.aligned.m8n8.x4.shared.b16 {%0,%1,%2,%3}, [%4];"
                    : "=r"(af[mi][0]), "=r"(af[mi][1]), "=r"(af[mi][2]), "=r"(af[mi][3])
                    : "r"(aLd[mi] + soC + ki * 32));
#pragma unroll
            for (int nb = 0; nb < 2; nb++)
                asm volatile("ldmatrix.sync.aligned.m8n8.x4.shared.b16 {%0,%1,%2,%3}, [%4];"
                    : "=r"(bf_[nb][0]), "=r"(bf_[nb][1]), "=r"(bf_[nb][2]), "=r"(bf_[nb][3])
                    : "r"(bLd[nb] + soC + ki * 32));
#pragma unroll
            for (int mi = 0; mi < 4; mi++)
#pragma unroll
                for (int ni = 0; ni < 4; ni++) {
                    u32 b0 = bf_[ni >> 1][(ni & 1) * 2];
                    u32 b1 = bf_[ni >> 1][(ni & 1) * 2 + 1];
                    asm volatile(
                        "mma.sync.aligned.m16n8k16.row.col.f32.bf16.bf16.f32 "
                        "{%0,%1,%2,%3}, {%4,%5,%6,%7}, {%8,%9}, {%0,%1,%2,%3};"
                        : "+f"(acc[mi][ni][0]), "+f"(acc[mi][ni][1]),
                          "+f"(acc[mi][ni][2]), "+f"(acc[mi][ni][3])
                        : "r"(af[mi][0]), "r"(af[mi][1]), "r"(af[mi][2]), "r"(af[mi][3]),
                          "r"(b0), "r"(b1));
                }
        }
        soC += STGB; if (soC == 3 * STGB) soC = 0;
        soI += STGB; if (soI == 3 * STGB) soI = 0;
    }

    // ---- epilogue ----
#pragma unroll
    for (int mi = 0; mi < 4; mi++) {
        int r0 = m0 + wm * 64 + mi * 16 + (lane >> 2);
        int r1 = r0 + 8;
        float an0 = 0.f, an1 = 0.f;
        if (MODE == 1) {
            an0 = (r0 < Mloc) ? anp[r0] : 0.f;
            an1 = (r1 < Mloc) ? anp[r1] : 0.f;
        }
#pragma unroll
        for (int ni = 0; ni < 4; ni++) {
            int c0 = n0 + wn * 32 + ni * 8 + (lane & 3) * 2;
            float v0 = acc[mi][ni][0], v1 = acc[mi][ni][1];
            float v2 = acc[mi][ni][2], v3 = acc[mi][ni][3];
            if (MODE == 1) {
                float b0 = (c0 < Nloc) ? bnp[c0] : 0.f;
                float b1 = (c0 + 1 < Nloc) ? bnp[c0 + 1] : 0.f;
                v0 = sqrtf(fmaxf(an0 + b0 - 2.f * v0, 0.f));
                v1 = sqrtf(fmaxf(an0 + b1 - 2.f * v1, 0.f));
                v2 = sqrtf(fmaxf(an1 + b0 - 2.f * v2, 0.f));
                v3 = sqrtf(fmaxf(an1 + b1 - 2.f * v3, 0.f));
            }
            if (r0 < Mloc) {
                if (c0 < Nloc)     C[(size_t)r0 * ldc + c0]     = v0;
                if (c0 + 1 < Nloc) C[(size_t)r0 * ldc + c0 + 1] = v1;
            }
            if (r1 < Mloc) {
                if (c0 < Nloc)     C[(size_t)r1 * ldc + c0]     = v2;
                if (c0 + 1 < Nloc) C[(size_t)r1 * ldc + c0 + 1] = v3;
            }
            if (MODE == 1 && mirror) {     // SD symmetry: store transpose too
                if (c0 < Nloc) {
                    if (r0 < Mloc) C[(size_t)c0 * ldc + r0] = v0;
                    if (r1 < Mloc) C[(size_t)c0 * ldc + r1] = v2;
                }
                if (c0 + 1 < Nloc) {
                    if (r0 < Mloc) C[(size_t)(c0 + 1) * ldc + r0] = v1;
                    if (r1 < Mloc) C[(size_t)(c0 + 1) * ldc + r1] = v3;
                }
            }
        }
    }
}

// ---------------- embedding build: relu(P[f0]+Q[f1]+b) -> hi/lo bf16 + norm ------
__global__ void k_embed(const float* __restrict__ bias) {
    int row = blockIdx.x;         // [0, NQT+NST)
    int tid = threadIdx.x;        // 256
    __nv_bfloat16 *dh, *dl;
    float* nout;
    int f0, f1;
    if (row < NQT) {
        int n = row / TT, t = row % TT;
        f0 = n * SEQ + c_p0[t];
        f1 = n * SEQ + c_p1[t];
        dh = g_QEh + (size_t)row * D; dl = g_QEl + (size_t)row * D; nout = &g_qn[row];
    } else {
        int si = row - NQT;
        int c = si / 225, rr = si % 225;
        int s = rr / TT, t = rr % TT;
        int base = QF + (c * SHOT + s) * SEQ;
        f0 = base + c_p0[t];
        f1 = base + c_p1[t];
        dh = g_SEh + (size_t)si * D; dl = g_SEl + (size_t)si * D; nout = &g_sn[si];
    }
    const float4* a0 = (const float4*)(g_EF + (size_t)f0 * 4096);          // P half
    const float4* a1 = (const float4*)(g_EF + (size_t)f1 * 4096 + D);      // Q half
    const float4* bb = (const float4*)bias;
    float nrm = 0.f;
    for (int v = tid; v < D / 4; v += 256) {
        float4 x = a0[v], y = a1[v], z = bb[v];
        float r0 = fmaxf(x.x + y.x + z.x, 0.f);
        float r1 = fmaxf(x.y + y.y + z.y, 0.f);
        float r2 = fmaxf(x.z + y.z + z.z, 0.f);
        float r3 = fmaxf(x.w + y.w + z.w, 0.f);
        nrm += r0 * r0 + r1 * r1 + r2 * r2 + r3 * r3;
        __nv_bfloat16 h0 = __float2bfloat16(r0), h1 = __float2bfloat16(r1);
        __nv_bfloat16 h2 = __float2bfloat16(r2), h3 = __float2bfloat16(r3);
        ((__nv_bfloat162*)dh)[v * 2]     = __nv_bfloat162(h0, h1);
        ((__nv_bfloat162*)dh)[v * 2 + 1] = __nv_bfloat162(h2, h3);
        ((__nv_bfloat162*)dl)[v * 2]     = __nv_bfloat162(
            __float2bfloat16(r0 - __bfloat162float(h0)),
            __float2bfloat16(r1 - __bfloat162float(h1)));
        ((__nv_bfloat162*)dl)[v * 2 + 1] = __nv_bfloat162(
            __float2bfloat16(r2 - __bfloat162float(h2)),
            __float2bfloat16(r3 - __bfloat162float(h3)));
    }
    __shared__ float sred[256];
    sred[tid] = nrm; __syncthreads();
    for (int s = 128; s; s >>= 1) {
        if (tid < s) sred[tid] += sred[tid + s];
        __syncthreads();
    }
    if (tid == 0) *nout = sred[0];
}

// ---------------- per-(class, query-tuple) reductions ----------------
__global__ void k_classred() {
    int w = (blockIdx.x * blockDim.x + threadIdx.x) >> 5;
    int lane = threadIdx.x & 31;
    if (w >= WAY * NQT) return;
    int c = w / NQT, qi = w % NQT;
    const float* row = g_DQ + (size_t)qi * NST + c * 225;
    float best = -1.f; int bidx = 0;
    float g0 = -1.f, g1 = -1.f, g2 = -1.f, g3 = -1.f, g4 = -1.f;
    for (int j = lane; j < 225; j += 32) {
        float v = row[j];
        if (v > best) { best = v; bidx = j; }
        int s = j % 5;
        if      (s == 0) g0 = fmaxf(g0, v);
        else if (s == 1) g1 = fmaxf(g1, v);
        else if (s == 2) g2 = fmaxf(g2, v);
        else if (s == 3) g3 = fmaxf(g3, v);
        else             g4 = fmaxf(g4, v);
    }
#pragma unroll
    for (int off = 16; off; off >>= 1) {
        float ob = __shfl_down_sync(0xffffffff, best, off);
        int   oi = __shfl_down_sync(0xffffffff, bidx, off);
        if (ob > best || (ob == best && oi < bidx)) { best = ob; bidx = oi; }
        g0 = fmaxf(g0, __shfl_down_sync(0xffffffff, g0, off));
        g1 = fmaxf(g1, __shfl_down_sync(0xffffffff, g1, off));
        g2 = fmaxf(g2, __shfl_down_sync(0xffffffff, g2, off));
        g3 = fmaxf(g3, __shfl_down_sync(0xffffffff, g3, off));
        g4 = fmaxf(g4, __shfl_down_sync(0xffffffff, g4, off));
    }
    if (lane == 0) {
        g_rowmax[w] = best;
        g_pos[w]    = bidx;
        g_ave[w]    = (g0 + g1 + g2 + g3 + g4) * 0.2f;
    }
}

// ---------------- record accumulation ----------------
__global__ void k_record() {
    int c = blockIdx.y;
    int tid = threadIdx.x;                 // 128
    __shared__ int srec[NST];
    for (int j = tid; j < NST; j += 128) srec[j] = 0;
    __syncthreads();
    int q0 = blockIdx.x * 125;
    for (int qi = q0; qi < q0 + 125; qi++) {
        int   p = g_pos[c * NQT + qi];
        float a = g_ave[c * NQT + qi];
        const float* row = g_SD + (size_t)(c * 225 + p) * NST;
        for (int j = tid; j < NST; j += 128)
            srec[j] += (row[j] > a) ? 1 : 0;
    }
    __syncthreads();
    for (int j = tid; j < NST; j += 128)
        atomicAdd(&g_record[c * NST + j], srec[j]);
}

// ---------------- threshold + mask + msum ----------------
__global__ void k_mask() {
    int c = blockIdx.x;
    int tid = threadIdx.x;                 // 256
    __shared__ float sred[256];
    __shared__ int   snz[256];
    __shared__ float s_thr;
    float msum_acc = 0.f;
    for (int m = 0; m < WAY; m++) {
        if (m == c) {
            if (tid < 225) g_mask[c * NST + m * 225 + tid] = 0.f;
            continue;
        }
        int rec = 0;
        if (tid < 225) rec = g_record[c * NST + m * 225 + tid];
        sred[tid] = (tid < 225) ? (float)rec : 0.f;
        snz[tid]  = (tid < 225 && rec != 0) ? 1 : 0;
        __syncthreads();
        for (int s = 128; s; s >>= 1) {
            if (tid < s) { sred[tid] += sred[tid + s]; snz[tid] += snz[tid + s]; }
            __syncthreads();
        }
        if (tid == 0) s_thr = sred[0] / fmaxf((float)snz[0], 1.f);
        __syncthreads();
        if (tid < 225) {
            float mk = ((float)rec < s_thr) ? 1.f : 0.f;
            g_mask[c * NST + m * 225 + tid] = mk;
            msum_acc += mk;
        }
        __syncthreads();
    }
    sred[tid] = msum_acc; __syncthreads();
    for (int s = 128; s; s >>= 1) {
        if (tid < s) sred[tid] += sred[tid + s];
        __syncthreads();
    }
    if (tid == 0) g_msum[c] = fmaxf(sred[0], 1.f);
}

// ---------------- masked mean -> contrast ----------------
__global__ void k_contrast() {
    int qi = blockIdx.x;
    int tid = threadIdx.x;                 // 128
    const float* row = g_DQ + (size_t)qi * NST;
    float a0 = 0.f, a1 = 0.f, a2 = 0.f, a3 = 0.f, a4 = 0.f;
    for (int j = tid; j < NST; j += 128) {
        float d = row[j];
        a0 += d * g_mask[0 * NST + j];
        a1 += d * g_mask[1 * NST + j];
        a2 += d * g_mask[2 * NST + j];
        a3 += d * g_mask[3 * NST + j];
        a4 += d * g_mask[4 * NST + j];
    }
    __shared__ float red[WAY][128];
    red[0][tid] = a0; red[1][tid] = a1; red[2][tid] = a2;
    red[3][tid] = a3; red[4][tid] = a4;
    __syncthreads();
    for (int s = 64; s; s >>= 1) {
        if (tid < s)
#pragma unroll
            for (int cc = 0; cc < WAY; cc++) red[cc][tid] += red[cc][tid + s];
        __syncthreads();
    }
    if (tid < WAY) {
        float val = red[tid][0] / g_msum[tid] * (1.f / (4.f * 45.f));
        atomicAdd(&g_contrast[(qi / TT) * WAY + tid], val);
    }
}

// ---------------- final outputs ----------------
__global__ void k_final(float* __restrict__ out, int out_size) {
    int idx = blockIdx.x * blockDim.x + threadIdx.x;
    if (idx >= NQ * WAY) return;
    int n = idx / WAY, c = idx % WAY;
    float s = 0.f;
    for (int t = 0; t < TT; t++) s += g_rowmax[c * NQT + n * TT + t];
    float dm = s * (1.f / 45.f);
    float ct = g_contrast[idx];
    float lg = dm / (ct + dm);
    if (idx < out_size) out[idx] = dm;
    if (NQ * WAY + idx < out_size) out[NQ * WAY + idx] = lg;
}

// ---------------- launch ----------------
extern "C" void kernel_launch(void* const* d_in, const int* in_sizes, int n_in,
                              void* d_out, int out_size) {
    const float* support = (const float*)d_in[0];   // [25,10,2048]
    const float* queries = (const float*)d_in[2];   // [75,10,2048]
    const float* W       = (const float*)d_in[3];   // [2048,4096]
    const float* bias    = (const float*)d_in[4];   // [2048]
    float* out = (float*)d_out;

    // 60 KB dynamic smem for the 3-stage ring (attribute set is idempotent,
    // host-side, not a stream op -> graph-capture safe)
    cudaFuncSetAttribute(gemm_mma<1>, cudaFuncAttributeMaxDynamicSharedMemorySize, SMEM_DYN);
    cudaFuncSetAttribute(gemm_mma<2>, cudaFuncAttributeMaxDynamicSharedMemorySize, SMEM_DYN);

    // hi/lo conversion (float4 vectorized)
    k_cvt<<<(NF * D / 4 + 4096 * D / 4 + 255) / 256, 256>>>(queries, support, W);

    // embedding GEMM: EF[1000, 4096] = frames @ Wmap^T  (mma.sync bf16, K=6144)
    gemm_mma<2><<<dim3(32, 8), 256, SMEM_DYN>>>();

    k_embed<<<NQT + NST, 256>>>(bias);

    // distance GEMMs: 243 DQ tiles + 45 SD upper-triangle tiles = 288 CTAs (one wave)
    gemm_mma<1><<<288, 256, SMEM_DYN>>>();

    // init only feeds k_record / k_contrast; launched late (ncu window lands on GEMMs)
    k_init<<<22, 256>>>();

    k_classred<<<2110, 256>>>();
    k_record<<<dim3(27, WAY), 128>>>();
    k_mask<<<WAY, 256>>>();
    k_contrast<<<NQT, 128>>>();
    k_final<<<2, 256>>>(out, out_size);
}